// round 2
// baseline (speedup 1.0000x reference)
#include <cuda_runtime.h>
#include <math.h>

#define D 1024
#define NH 16
#define DH 64
#define BB 2
#define SS 2048
#define MTOK (BB*SS)       // 4096
#define NEGV -1000000000.0f

// ---------------- scratch (device globals; no allocations) ----------------
__device__ float g_xln[MTOK*D];
__device__ float g_q[MTOK*D];
__device__ float g_k[MTOK*D];
__device__ float g_v[MTOK*D];
__device__ float g_ao[MTOK*D];
__device__ float g_h[MTOK*D];
__device__ float g_hln[MTOK*D];
__device__ float g_r[MTOK*D];
__device__ float g_z[MTOK*D];
__device__ float g_mid[(size_t)MTOK*4*D];

// ---------------- fused embedding + LayerNorm1 ----------------
__global__ __launch_bounds__(256) void embed_ln_kernel(
    const int* __restrict__ tids, const float* __restrict__ tok,
    const float* __restrict__ pos, const float* __restrict__ gam,
    const float* __restrict__ bet, float* __restrict__ out)
{
    int row = blockIdx.x;            // 0..4095
    int s   = row % SS;
    int t   = tids[row];
    const float* te = tok + (size_t)t * D;
    const float* pe = pos + (size_t)s * D;
    float v[4];
    float sum = 0.f, sq = 0.f;
#pragma unroll
    for (int i = 0; i < 4; i++) {
        int d = threadIdx.x + 256*i;
        float x = te[d] + pe[d];
        v[i] = x; sum += x; sq += x*x;
    }
    __shared__ float s1[256], s2[256];
    int tid = threadIdx.x;
    s1[tid] = sum; s2[tid] = sq; __syncthreads();
    for (int o = 128; o > 0; o >>= 1) {
        if (tid < o) { s1[tid] += s1[tid+o]; s2[tid] += s2[tid+o]; }
        __syncthreads();
    }
    float mu  = s1[0] * (1.f/D);
    float var = s2[0] * (1.f/D) - mu*mu;
    float rs  = rsqrtf(var + 1e-5f);
#pragma unroll
    for (int i = 0; i < 4; i++) {
        int d = threadIdx.x + 256*i;
        out[(size_t)row*D + d] = (v[i]-mu)*rs*gam[d] + bet[d];
    }
}

// ---------------- generic LayerNorm ----------------
__global__ __launch_bounds__(256) void ln_kernel(
    const float* __restrict__ X, const float* __restrict__ gam,
    const float* __restrict__ bet, float* __restrict__ out)
{
    int row = blockIdx.x;
    const float* x = X + (size_t)row*D;
    float v[4];
    float sum = 0.f, sq = 0.f;
#pragma unroll
    for (int i = 0; i < 4; i++) {
        int d = threadIdx.x + 256*i;
        float xx = x[d];
        v[i] = xx; sum += xx; sq += xx*xx;
    }
    __shared__ float s1[256], s2[256];
    int tid = threadIdx.x;
    s1[tid] = sum; s2[tid] = sq; __syncthreads();
    for (int o = 128; o > 0; o >>= 1) {
        if (tid < o) { s1[tid] += s1[tid+o]; s2[tid] += s2[tid+o]; }
        __syncthreads();
    }
    float mu  = s1[0] * (1.f/D);
    float var = s2[0] * (1.f/D) - mu*mu;
    float rs  = rsqrtf(var + 1e-5f);
#pragma unroll
    for (int i = 0; i < 4; i++) {
        int d = threadIdx.x + 256*i;
        out[(size_t)row*D + d] = (v[i]-mu)*rs*gam[d] + bet[d];
    }
}

// ---------------- SGEMM: C = A@B + bias [, GELU] [, +res] ----------------
// A: [M,K] row-major, B: [K,N] row-major. 64x64 tile, BK=16, 256 thr, 4x4/thr.
template<int GELU, int RES>
__global__ __launch_bounds__(256) void sgemm_kernel(
    const float* __restrict__ A, const float* __restrict__ Bm,
    const float* __restrict__ bias, const float* __restrict__ res,
    float* __restrict__ C, int M, int N, int K)
{
    __shared__ float As[16][65];
    __shared__ float Bs[16][64];
    int bm = blockIdx.y * 64, bn = blockIdx.x * 64;
    int tx = threadIdx.x & 15, ty = threadIdx.x >> 4;
    float acc[4][4] = {};
    for (int k0 = 0; k0 < K; k0 += 16) {
#pragma unroll
        for (int rr = 0; rr < 4; rr++) {
            int idx = threadIdx.x + 256*rr;
            int m  = idx >> 4, kk = idx & 15;
            As[kk][m] = A[(size_t)(bm+m)*K + k0 + kk];
            int k2 = idx >> 6, n = idx & 63;
            Bs[k2][n] = Bm[(size_t)(k0+k2)*N + bn + n];
        }
        __syncthreads();
#pragma unroll
        for (int kk = 0; kk < 16; kk++) {
            float a[4], b[4];
#pragma unroll
            for (int x = 0; x < 4; x++) { a[x] = As[kk][ty*4+x]; b[x] = Bs[kk][tx*4+x]; }
#pragma unroll
            for (int x = 0; x < 4; x++)
#pragma unroll
                for (int y = 0; y < 4; y++)
                    acc[x][y] += a[x]*b[y];
        }
        __syncthreads();
    }
#pragma unroll
    for (int x = 0; x < 4; x++) {
        int m = bm + ty*4 + x;
#pragma unroll
        for (int y = 0; y < 4; y++) {
            int n = bn + tx*4 + y;
            float val = acc[x][y] + bias[n];
            if (GELU) val = 0.5f*val*(1.0f + erff(val*0.70710678118654752f));
            if (RES)  val += res[(size_t)m*N + n];
            C[(size_t)m*N + n] = val;
        }
    }
}

// ---------------- flash attention (1 query/thread, K/V in smem) ----------------
// Q,K,V,O all laid out [B, S, H*DH] (head h occupies columns h*64..h*64+63).
__global__ __launch_bounds__(256) void attn_kernel(
    const float* __restrict__ Qb, const float* __restrict__ Kb,
    const float* __restrict__ Vb, const int* __restrict__ ids,
    float* __restrict__ O, int causal)
{
    __shared__ float Ks[64][DH];
    __shared__ float Vs[64][DH];
    __shared__ float padv[64];
    int b = blockIdx.z, h = blockIdx.y;
    int qb = blockIdx.x * 256;
    int qi = qb + threadIdx.x;

    const float* qrow = Qb + ((size_t)(b*SS + qi))*D + h*DH;
    float q[DH];
#pragma unroll
    for (int d = 0; d < DH; d++) q[d] = qrow[d];

    float m = -3.0e38f, l = 0.f;
    float acc[DH] = {};

    int ktend = causal ? ((qb + 255) >> 6) : (SS/64 - 1);
    for (int kt = 0; kt <= ktend; kt++) {
        int kbase = kt * 64;
#pragma unroll
        for (int rr = 0; rr < 16; rr++) {
            int idx = threadIdx.x + 256*rr;
            int j = idx >> 6, d = idx & 63;
            size_t g = ((size_t)(b*SS + kbase + j))*D + h*DH + d;
            Ks[j][d] = Kb[g];
            Vs[j][d] = Vb[g];
        }
        if (threadIdx.x < 64)
            padv[threadIdx.x] = (ids[b*SS + kbase + threadIdx.x] == 0) ? NEGV : 0.f;
        __syncthreads();

#pragma unroll 1
        for (int j = 0; j < 64; j++) {
            int kj = kbase + j;
            float s = 0.f;
#pragma unroll
            for (int d = 0; d < DH; d++) s += q[d]*Ks[j][d];
            float logit = s*0.125f + padv[j];
            if (causal && kj > qi) logit += NEGV;
            if (logit <= m) {
                float p = __expf(logit - m);
                l += p;
#pragma unroll
                for (int d = 0; d < DH; d++) acc[d] += p*Vs[j][d];
            } else {
                float corr = __expf(m - logit);
                m = logit;
                l = l*corr + 1.f;
#pragma unroll
                for (int d = 0; d < DH; d++) acc[d] = acc[d]*corr + Vs[j][d];
            }
        }
        __syncthreads();
    }
    float inv = 1.f / l;
    float* orow = O + ((size_t)(b*SS + qi))*D + h*DH;
#pragma unroll
    for (int d = 0; d < DH; d++) orow[d] = acc[d]*inv;
}

// ---------------- host ----------------
extern "C" void kernel_launch(void* const* d_in, const int* in_sizes, int n_in,
                              void* d_out, int out_size)
{
    const float* emb  = (const float*)d_in[0];
    const int*   iids = (const int*)  d_in[1];
    const int*   tids = (const int*)  d_in[2];
    const float* tok  = (const float*)d_in[3];
    const float* pos  = (const float*)d_in[4];
    const float* ln1g = (const float*)d_in[5];
    const float* ln1b = (const float*)d_in[6];
    const float* q1w  = (const float*)d_in[7];
    const float* q1b  = (const float*)d_in[8];
    const float* k1w  = (const float*)d_in[9];
    const float* k1b  = (const float*)d_in[10];
    const float* v1w  = (const float*)d_in[11];
    const float* v1b  = (const float*)d_in[12];
    const float* o1w  = (const float*)d_in[13];
    const float* o1b  = (const float*)d_in[14];
    const float* ln2g = (const float*)d_in[15];
    const float* ln2b = (const float*)d_in[16];
    const float* q2w  = (const float*)d_in[17];
    const float* q2b  = (const float*)d_in[18];
    const float* k2w  = (const float*)d_in[19];
    const float* k2b  = (const float*)d_in[20];
    const float* v2w  = (const float*)d_in[21];
    const float* v2b  = (const float*)d_in[22];
    const float* o2w  = (const float*)d_in[23];
    const float* o2b  = (const float*)d_in[24];
    const float* ln3g = (const float*)d_in[25];
    const float* ln3b = (const float*)d_in[26];
    const float* w1   = (const float*)d_in[27];
    const float* b1   = (const float*)d_in[28];
    const float* w2   = (const float*)d_in[29];
    const float* b2   = (const float*)d_in[30];
    float* out = (float*)d_out;

    float *xln, *q, *k, *v, *ao, *h, *hln, *r, *z, *mid;
    cudaGetSymbolAddress((void**)&xln, g_xln);
    cudaGetSymbolAddress((void**)&q,   g_q);
    cudaGetSymbolAddress((void**)&k,   g_k);
    cudaGetSymbolAddress((void**)&v,   g_v);
    cudaGetSymbolAddress((void**)&ao,  g_ao);
    cudaGetSymbolAddress((void**)&h,   g_h);
    cudaGetSymbolAddress((void**)&hln, g_hln);
    cudaGetSymbolAddress((void**)&r,   g_r);
    cudaGetSymbolAddress((void**)&z,   g_z);
    cudaGetSymbolAddress((void**)&mid, g_mid);

    dim3 gProj(D/64, MTOK/64);          // N=1024
    dim3 gMlp1(4*D/64, MTOK/64);        // N=4096
    dim3 gAttn(SS/256, NH, BB);

    // embedding + LN1
    embed_ln_kernel<<<MTOK, 256>>>(tids, tok, pos, ln1g, ln1b, xln);
    // self-attention q/k/v projections
    sgemm_kernel<0,0><<<gProj, 256>>>(xln, q1w, q1b, nullptr, q, MTOK, D, D);
    sgemm_kernel<0,0><<<gProj, 256>>>(xln, k1w, k1b, nullptr, k, MTOK, D, D);
    sgemm_kernel<0,0><<<gProj, 256>>>(xln, v1w, v1b, nullptr, v, MTOK, D, D);
    // causal self-attention (pad mask over target_ids)
    attn_kernel<<<gAttn, 256>>>(q, k, v, tids, ao, 1);
    // out-proj + residual (h = xln + attn@W + b)
    sgemm_kernel<0,1><<<gProj, 256>>>(ao, o1w, o1b, xln, h, MTOK, D, D);
    // LN2
    ln_kernel<<<MTOK, 256>>>(h, ln2g, ln2b, hln);
    // cross-attention projections (Q from hln; K,V from encoder states)
    sgemm_kernel<0,0><<<gProj, 256>>>(hln, q2w, q2b, nullptr, q, MTOK, D, D);
    sgemm_kernel<0,0><<<gProj, 256>>>(emb, k2w, k2b, nullptr, k, MTOK, D, D);
    sgemm_kernel<0,0><<<gProj, 256>>>(emb, v2w, v2b, nullptr, v, MTOK, D, D);
    // cross-attention (no causal; pad mask over input_ids)
    attn_kernel<<<gAttn, 256>>>(q, k, v, iids, ao, 0);
    // out-proj + residual (r = hln + cross@W + b)
    sgemm_kernel<0,1><<<gProj, 256>>>(ao, o2w, o2b, hln, r, MTOK, D, D);
    // LN3
    ln_kernel<<<MTOK, 256>>>(r, ln3g, ln3b, z);
    // MLP: mid = gelu(z@W1 + b1); out = mid@W2 + b2 + r
    sgemm_kernel<1,0><<<gMlp1, 256>>>(z, w1, b1, nullptr, mid, MTOK, 4*D, D);
    sgemm_kernel<0,1><<<gProj, 256>>>(mid, w2, b2, r, out, MTOK, D, 4*D);
}

// round 4
// speedup vs baseline: 1.6430x; 1.6430x over previous
#include <cuda_runtime.h>
#include <math.h>
#include <stdint.h>

#define D 1024
#define NH 16
#define DH 64
#define BB 2
#define SS 2048
#define MTOK (BB*SS)       // 4096
#define NEGV -1000000000.0f

// ---------------- scratch (device globals; no allocations) ----------------
__device__ float g_xln[MTOK*D];
__device__ float g_q[MTOK*D];
__device__ float g_k[MTOK*D];
__device__ float g_v[MTOK*D];
__device__ float g_ao[MTOK*D];
__device__ float g_h[MTOK*D];
__device__ float g_hln[MTOK*D];
__device__ float g_r[MTOK*D];
__device__ float g_z[MTOK*D];
__device__ float g_mid[(size_t)MTOK*4*D];

// ---------------- fused embedding + LayerNorm1 ----------------
__global__ __launch_bounds__(256) void embed_ln_kernel(
    const int* __restrict__ tids, const float* __restrict__ tok,
    const float* __restrict__ pos, const float* __restrict__ gam,
    const float* __restrict__ bet, float* __restrict__ out)
{
    int row = blockIdx.x;
    int s   = row % SS;
    int t   = tids[row];
    const float* te = tok + (size_t)t * D;
    const float* pe = pos + (size_t)s * D;
    float v[4];
    float sum = 0.f, sq = 0.f;
#pragma unroll
    for (int i = 0; i < 4; i++) {
        int d = threadIdx.x + 256*i;
        float x = te[d] + pe[d];
        v[i] = x; sum += x; sq += x*x;
    }
    __shared__ float s1[256], s2[256];
    int tid = threadIdx.x;
    s1[tid] = sum; s2[tid] = sq; __syncthreads();
    for (int o = 128; o > 0; o >>= 1) {
        if (tid < o) { s1[tid] += s1[tid+o]; s2[tid] += s2[tid+o]; }
        __syncthreads();
    }
    float mu  = s1[0] * (1.f/D);
    float var = s2[0] * (1.f/D) - mu*mu;
    float rs  = rsqrtf(var + 1e-5f);
#pragma unroll
    for (int i = 0; i < 4; i++) {
        int d = threadIdx.x + 256*i;
        out[(size_t)row*D + d] = (v[i]-mu)*rs*gam[d] + bet[d];
    }
}

// ---------------- generic LayerNorm ----------------
__global__ __launch_bounds__(256) void ln_kernel(
    const float* __restrict__ X, const float* __restrict__ gam,
    const float* __restrict__ bet, float* __restrict__ out)
{
    int row = blockIdx.x;
    const float* x = X + (size_t)row*D;
    float v[4];
    float sum = 0.f, sq = 0.f;
#pragma unroll
    for (int i = 0; i < 4; i++) {
        int d = threadIdx.x + 256*i;
        float xx = x[d];
        v[i] = xx; sum += xx; sq += xx*xx;
    }
    __shared__ float s1[256], s2[256];
    int tid = threadIdx.x;
    s1[tid] = sum; s2[tid] = sq; __syncthreads();
    for (int o = 128; o > 0; o >>= 1) {
        if (tid < o) { s1[tid] += s1[tid+o]; s2[tid] += s2[tid+o]; }
        __syncthreads();
    }
    float mu  = s1[0] * (1.f/D);
    float var = s2[0] * (1.f/D) - mu*mu;
    float rs  = rsqrtf(var + 1e-5f);
#pragma unroll
    for (int i = 0; i < 4; i++) {
        int d = threadIdx.x + 256*i;
        out[(size_t)row*D + d] = (v[i]-mu)*rs*gam[d] + bet[d];
    }
}

// ---------------- tf32 tensor-core GEMM ----------------
// C[M,N] = A[M,K] @ B[K,N] + bias [, GELU] [, + res]
// 128x128 CTA tile, BK=16, 256 threads (8 warps as 2x4), warp tile 64x32,
// mma.sync.m16n8k8.tf32, double-buffered smem with register staging.
__device__ __forceinline__ uint32_t f2tf(float x){
    uint32_t r; asm("cvt.rna.tf32.f32 %0, %1;" : "=r"(r) : "f"(x)); return r;
}

template<int GELU, int RES>
__global__ __launch_bounds__(256) void mma_gemm(
    const float* __restrict__ A, const float* __restrict__ Bm,
    const float* __restrict__ bias, const float* __restrict__ res,
    float* __restrict__ C, int M, int N, int K)
{
    __shared__ __align__(16) uint32_t As[2][128][20];   // [buf][m][k], pitch 20
    __shared__ __align__(16) uint32_t Bs[2][16][132];   // [buf][k][n], pitch 132

    const int tid  = threadIdx.x;
    const int lane = tid & 31;
    const int warp = tid >> 5;
    const int wm   = warp >> 2;          // 0..1  (64 rows each)
    const int wn   = warp & 3;           // 0..3  (32 cols each)
    const int bm   = blockIdx.y * 128;
    const int bn   = blockIdx.x * 128;

    // global load mapping
    const int arow = tid >> 2;           // 0..63 (+64)
    const int acol = (tid & 3) * 4;
    const int brow = tid >> 5;           // 0..7 (+8)
    const int bcol = (tid & 31) * 4;

    const float* gA0 = A + (size_t)(bm + arow)      * K + acol;
    const float* gA1 = A + (size_t)(bm + arow + 64) * K + acol;
    const float* gB0 = Bm + (size_t)brow       * N + bn + bcol;
    const float* gB1 = Bm + (size_t)(brow + 8) * N + bn + bcol;

    float acc[4][4][4];
#pragma unroll
    for (int i = 0; i < 4; i++)
#pragma unroll
        for (int j = 0; j < 4; j++)
#pragma unroll
            for (int c = 0; c < 4; c++) acc[i][j][c] = 0.f;

    const int T = K >> 4;

    // prologue: tile 0
    {
        float4 a0 = *(const float4*)gA0;
        float4 a1 = *(const float4*)gA1;
        float4 b0 = *(const float4*)gB0;
        float4 b1 = *(const float4*)gB1;
        *(uint4*)&As[0][arow][acol]      = make_uint4(f2tf(a0.x),f2tf(a0.y),f2tf(a0.z),f2tf(a0.w));
        *(uint4*)&As[0][arow+64][acol]   = make_uint4(f2tf(a1.x),f2tf(a1.y),f2tf(a1.z),f2tf(a1.w));
        *(uint4*)&Bs[0][brow][bcol]      = make_uint4(f2tf(b0.x),f2tf(b0.y),f2tf(b0.z),f2tf(b0.w));
        *(uint4*)&Bs[0][brow+8][bcol]    = make_uint4(f2tf(b1.x),f2tf(b1.y),f2tf(b1.z),f2tf(b1.w));
    }
    __syncthreads();

    int buf = 0;
    for (int t = 0; t < T; t++) {
        float4 na0, na1, nb0, nb1;
        if (t + 1 < T) {
            int k0 = (t + 1) << 4;
            na0 = *(const float4*)(gA0 + k0);
            na1 = *(const float4*)(gA1 + k0);
            nb0 = *(const float4*)(gB0 + (size_t)k0 * N);
            nb1 = *(const float4*)(gB1 + (size_t)k0 * N);
        }
#pragma unroll
        for (int ks = 0; ks < 2; ks++) {
            const int kk = ks * 8;
            uint32_t af[4][4], bf[4][2];
#pragma unroll
            for (int mt = 0; mt < 4; mt++) {
                int r0 = wm*64 + mt*16 + (lane >> 2);
                int kc = kk + (lane & 3);
                af[mt][0] = As[buf][r0    ][kc];
                af[mt][1] = As[buf][r0 + 8][kc];
                af[mt][2] = As[buf][r0    ][kc + 4];
                af[mt][3] = As[buf][r0 + 8][kc + 4];
            }
#pragma unroll
            for (int nt = 0; nt < 4; nt++) {
                int cn = wn*32 + nt*8 + (lane >> 2);
                int kc = kk + (lane & 3);
                bf[nt][0] = Bs[buf][kc    ][cn];
                bf[nt][1] = Bs[buf][kc + 4][cn];
            }
#pragma unroll
            for (int mt = 0; mt < 4; mt++)
#pragma unroll
                for (int nt = 0; nt < 4; nt++) {
                    asm volatile(
                        "mma.sync.aligned.m16n8k8.row.col.f32.tf32.tf32.f32 "
                        "{%0,%1,%2,%3}, {%4,%5,%6,%7}, {%8,%9}, {%0,%1,%2,%3};"
                        : "+f"(acc[mt][nt][0]), "+f"(acc[mt][nt][1]),
                          "+f"(acc[mt][nt][2]), "+f"(acc[mt][nt][3])
                        : "r"(af[mt][0]), "r"(af[mt][1]), "r"(af[mt][2]), "r"(af[mt][3]),
                          "r"(bf[nt][0]), "r"(bf[nt][1]));
                }
        }
        if (t + 1 < T) {
            int nb = buf ^ 1;
            *(uint4*)&As[nb][arow][acol]    = make_uint4(f2tf(na0.x),f2tf(na0.y),f2tf(na0.z),f2tf(na0.w));
            *(uint4*)&As[nb][arow+64][acol] = make_uint4(f2tf(na1.x),f2tf(na1.y),f2tf(na1.z),f2tf(na1.w));
            *(uint4*)&Bs[nb][brow][bcol]    = make_uint4(f2tf(nb0.x),f2tf(nb0.y),f2tf(nb0.z),f2tf(nb0.w));
            *(uint4*)&Bs[nb][brow+8][bcol]  = make_uint4(f2tf(nb1.x),f2tf(nb1.y),f2tf(nb1.z),f2tf(nb1.w));
            __syncthreads();
            buf = nb;
        }
    }

    // epilogue
#pragma unroll
    for (int mt = 0; mt < 4; mt++) {
#pragma unroll
        for (int nt = 0; nt < 4; nt++) {
            int m0 = bm + wm*64 + mt*16 + (lane >> 2);
            int n0 = bn + wn*32 + nt*8 + (lane & 3)*2;
#pragma unroll
            for (int half = 0; half < 2; half++) {
                int m = m0 + half*8;
                float v0 = acc[mt][nt][half*2]     + bias[n0];
                float v1 = acc[mt][nt][half*2 + 1] + bias[n0 + 1];
                if (GELU) {
                    v0 = 0.5f*v0*(1.0f + erff(v0*0.70710678118654752f));
                    v1 = 0.5f*v1*(1.0f + erff(v1*0.70710678118654752f));
                }
                if (RES) {
                    v0 += res[(size_t)m*N + n0];
                    v1 += res[(size_t)m*N + n0 + 1];
                }
                *(float2*)&C[(size_t)m*N + n0] = make_float2(v0, v1);
            }
        }
    }
}

// ---------------- flash attention (1 query/thread, K/V in smem) ----------------
__global__ __launch_bounds__(256) void attn_kernel(
    const float* __restrict__ Qb, const float* __restrict__ Kb,
    const float* __restrict__ Vb, const int* __restrict__ ids,
    float* __restrict__ O, int causal)
{
    __shared__ float Ks[64][DH];
    __shared__ float Vs[64][DH];
    __shared__ float padv[64];
    int b = blockIdx.z, h = blockIdx.y;
    int qb = blockIdx.x * 256;
    int qi = qb + threadIdx.x;

    const float* qrow = Qb + ((size_t)(b*SS + qi))*D + h*DH;
    float q[DH];
#pragma unroll
    for (int d = 0; d < DH; d++) q[d] = qrow[d];

    float m = -3.0e38f, l = 0.f;
    float acc[DH] = {};

    int ktend = causal ? ((qb + 255) >> 6) : (SS/64 - 1);
    for (int kt = 0; kt <= ktend; kt++) {
        int kbase = kt * 64;
#pragma unroll
        for (int rr = 0; rr < 16; rr++) {
            int idx = threadIdx.x + 256*rr;
            int j = idx >> 6, d = idx & 63;
            size_t g = ((size_t)(b*SS + kbase + j))*D + h*DH + d;
            Ks[j][d] = Kb[g];
            Vs[j][d] = Vb[g];
        }
        if (threadIdx.x < 64)
            padv[threadIdx.x] = (ids[b*SS + kbase + threadIdx.x] == 0) ? NEGV : 0.f;
        __syncthreads();

#pragma unroll 1
        for (int j = 0; j < 64; j++) {
            int kj = kbase + j;
            float s = 0.f;
#pragma unroll
            for (int d = 0; d < DH; d++) s += q[d]*Ks[j][d];
            float logit = s*0.125f + padv[j];
            if (causal && kj > qi) logit += NEGV;
            if (logit <= m) {
                float p = __expf(logit - m);
                l += p;
#pragma unroll
                for (int d = 0; d < DH; d++) acc[d] += p*Vs[j][d];
            } else {
                float corr = __expf(m - logit);
                m = logit;
                l = l*corr + 1.f;
#pragma unroll
                for (int d = 0; d < DH; d++) acc[d] = acc[d]*corr + Vs[j][d];
            }
        }
        __syncthreads();
    }
    float inv = 1.f / l;
    float* orow = O + ((size_t)(b*SS + qi))*D + h*DH;
#pragma unroll
    for (int d = 0; d < DH; d++) orow[d] = acc[d]*inv;
}

// ---------------- host ----------------
extern "C" void kernel_launch(void* const* d_in, const int* in_sizes, int n_in,
                              void* d_out, int out_size)
{
    const float* emb  = (const float*)d_in[0];
    const int*   iids = (const int*)  d_in[1];
    const int*   tids = (const int*)  d_in[2];
    const float* tok  = (const float*)d_in[3];
    const float* pos  = (const float*)d_in[4];
    const float* ln1g = (const float*)d_in[5];
    const float* ln1b = (const float*)d_in[6];
    const float* q1w  = (const float*)d_in[7];
    const float* q1b  = (const float*)d_in[8];
    const float* k1w  = (const float*)d_in[9];
    const float* k1b  = (const float*)d_in[10];
    const float* v1w  = (const float*)d_in[11];
    const float* v1b  = (const float*)d_in[12];
    const float* o1w  = (const float*)d_in[13];
    const float* o1b  = (const float*)d_in[14];
    const float* ln2g = (const float*)d_in[15];
    const float* ln2b = (const float*)d_in[16];
    const float* q2w  = (const float*)d_in[17];
    const float* q2b  = (const float*)d_in[18];
    const float* k2w  = (const float*)d_in[19];
    const float* k2b  = (const float*)d_in[20];
    const float* v2w  = (const float*)d_in[21];
    const float* v2b  = (const float*)d_in[22];
    const float* o2w  = (const float*)d_in[23];
    const float* o2b  = (const float*)d_in[24];
    const float* ln3g = (const float*)d_in[25];
    const float* ln3b = (const float*)d_in[26];
    const float* w1   = (const float*)d_in[27];
    const float* b1   = (const float*)d_in[28];
    const float* w2   = (const float*)d_in[29];
    const float* b2   = (const float*)d_in[30];
    float* out = (float*)d_out;

    float *xln, *q, *k, *v, *ao, *h, *hln, *r, *z, *mid;
    cudaGetSymbolAddress((void**)&xln, g_xln);
    cudaGetSymbolAddress((void**)&q,   g_q);
    cudaGetSymbolAddress((void**)&k,   g_k);
    cudaGetSymbolAddress((void**)&v,   g_v);
    cudaGetSymbolAddress((void**)&ao,  g_ao);
    cudaGetSymbolAddress((void**)&h,   g_h);
    cudaGetSymbolAddress((void**)&hln, g_hln);
    cudaGetSymbolAddress((void**)&r,   g_r);
    cudaGetSymbolAddress((void**)&z,   g_z);
    cudaGetSymbolAddress((void**)&mid, g_mid);

    dim3 gProj(D/128, MTOK/128);        // (8, 32)
    dim3 gMlp1(4*D/128, MTOK/128);      // (32, 32)
    dim3 gAttn(SS/256, NH, BB);

    // embedding + LN1
    embed_ln_kernel<<<MTOK, 256>>>(tids, tok, pos, ln1g, ln1b, xln);
    // self-attention q/k/v projections
    mma_gemm<0,0><<<gProj, 256>>>(xln, q1w, q1b, nullptr, q, MTOK, D, D);
    mma_gemm<0,0><<<gProj, 256>>>(xln, k1w, k1b, nullptr, k, MTOK, D, D);
    mma_gemm<0,0><<<gProj, 256>>>(xln, v1w, v1b, nullptr, v, MTOK, D, D);
    // causal self-attention (pad mask over target_ids)
    attn_kernel<<<gAttn, 256>>>(q, k, v, tids, ao, 1);
    // out-proj + residual
    mma_gemm<0,1><<<gProj, 256>>>(ao, o1w, o1b, xln, h, MTOK, D, D);
    // LN2
    ln_kernel<<<MTOK, 256>>>(h, ln2g, ln2b, hln);
    // cross-attention projections
    mma_gemm<0,0><<<gProj, 256>>>(hln, q2w, q2b, nullptr, q, MTOK, D, D);
    mma_gemm<0,0><<<gProj, 256>>>(emb, k2w, k2b, nullptr, k, MTOK, D, D);
    mma_gemm<0,0><<<gProj, 256>>>(emb, v2w, v2b, nullptr, v, MTOK, D, D);
    // cross-attention (pad mask over input_ids)
    attn_kernel<<<gAttn, 256>>>(q, k, v, iids, ao, 0);
    // out-proj + residual
    mma_gemm<0,1><<<gProj, 256>>>(ao, o2w, o2b, hln, r, MTOK, D, D);
    // LN3
    ln_kernel<<<MTOK, 256>>>(r, ln3g, ln3b, z);
    // MLP
    mma_gemm<1,0><<<gMlp1, 256>>>(z, w1, b1, nullptr, mid, MTOK, 4*D, D);
    mma_gemm<0,1><<<gProj, 256>>>(mid, w2, b2, r, out, MTOK, D, 4*D);
}

// round 6
// speedup vs baseline: 3.6344x; 2.2121x over previous
#include <cuda_runtime.h>
#include <math.h>
#include <stdint.h>

#define D 1024
#define NH 16
#define DH 64
#define BB 2
#define SS 2048
#define MTOK (BB*SS)       // 4096
#define NEGV -1000000000.0f

// ---------------- scratch (device globals; no allocations) ----------------
__device__ float g_xln[MTOK*D];
__device__ float g_q[MTOK*D];
__device__ float g_k[MTOK*D];
__device__ float g_v[MTOK*D];
__device__ float g_ao[MTOK*D];
__device__ float g_h[MTOK*D];
__device__ float g_hln[MTOK*D];
__device__ float g_r[MTOK*D];
__device__ float g_z[MTOK*D];
__device__ float g_mid[(size_t)MTOK*4*D];

__device__ __forceinline__ uint32_t f2tf(float x){
    uint32_t r; asm("cvt.rna.tf32.f32 %0, %1;" : "=r"(r) : "f"(x)); return r;
}
__device__ __forceinline__ void mma8(float* c, const uint32_t* a, uint32_t b0, uint32_t b1){
    asm volatile(
        "mma.sync.aligned.m16n8k8.row.col.f32.tf32.tf32.f32 "
        "{%0,%1,%2,%3}, {%4,%5,%6,%7}, {%8,%9}, {%0,%1,%2,%3};"
        : "+f"(c[0]), "+f"(c[1]), "+f"(c[2]), "+f"(c[3])
        : "r"(a[0]), "r"(a[1]), "r"(a[2]), "r"(a[3]), "r"(b0), "r"(b1));
}

// ---------------- fused embedding + LayerNorm1 ----------------
__global__ __launch_bounds__(256) void embed_ln_kernel(
    const int* __restrict__ tids, const float* __restrict__ tok,
    const float* __restrict__ pos, const float* __restrict__ gam,
    const float* __restrict__ bet, float* __restrict__ out)
{
    int row = blockIdx.x;
    int s   = row % SS;
    int t   = tids[row];
    const float* te = tok + (size_t)t * D;
    const float* pe = pos + (size_t)s * D;
    float v[4];
    float sum = 0.f, sq = 0.f;
#pragma unroll
    for (int i = 0; i < 4; i++) {
        int d = threadIdx.x + 256*i;
        float x = te[d] + pe[d];
        v[i] = x; sum += x; sq += x*x;
    }
    __shared__ float s1[256], s2[256];
    int tid = threadIdx.x;
    s1[tid] = sum; s2[tid] = sq; __syncthreads();
    for (int o = 128; o > 0; o >>= 1) {
        if (tid < o) { s1[tid] += s1[tid+o]; s2[tid] += s2[tid+o]; }
        __syncthreads();
    }
    float mu  = s1[0] * (1.f/D);
    float var = s2[0] * (1.f/D) - mu*mu;
    float rs  = rsqrtf(var + 1e-5f);
#pragma unroll
    for (int i = 0; i < 4; i++) {
        int d = threadIdx.x + 256*i;
        out[(size_t)row*D + d] = (v[i]-mu)*rs*gam[d] + bet[d];
    }
}

// ---------------- generic LayerNorm ----------------
__global__ __launch_bounds__(256) void ln_kernel(
    const float* __restrict__ X, const float* __restrict__ gam,
    const float* __restrict__ bet, float* __restrict__ out)
{
    int row = blockIdx.x;
    const float* x = X + (size_t)row*D;
    float v[4];
    float sum = 0.f, sq = 0.f;
#pragma unroll
    for (int i = 0; i < 4; i++) {
        int d = threadIdx.x + 256*i;
        float xx = x[d];
        v[i] = xx; sum += xx; sq += xx*xx;
    }
    __shared__ float s1[256], s2[256];
    int tid = threadIdx.x;
    s1[tid] = sum; s2[tid] = sq; __syncthreads();
    for (int o = 128; o > 0; o >>= 1) {
        if (tid < o) { s1[tid] += s1[tid+o]; s2[tid] += s2[tid+o]; }
        __syncthreads();
    }
    float mu  = s1[0] * (1.f/D);
    float var = s2[0] * (1.f/D) - mu*mu;
    float rs  = rsqrtf(var + 1e-5f);
#pragma unroll
    for (int i = 0; i < 4; i++) {
        int d = threadIdx.x + 256*i;
        out[(size_t)row*D + d] = (v[i]-mu)*rs*gam[d] + bet[d];
    }
}

// ---------------- tf32 tensor-core GEMM (unchanged from R2) ----------------
template<int GELU, int RES>
__global__ __launch_bounds__(256) void mma_gemm(
    const float* __restrict__ A, const float* __restrict__ Bm,
    const float* __restrict__ bias, const float* __restrict__ res,
    float* __restrict__ C, int M, int N, int K)
{
    __shared__ __align__(16) uint32_t As[2][128][20];
    __shared__ __align__(16) uint32_t Bs[2][16][132];

    const int tid  = threadIdx.x;
    const int lane = tid & 31;
    const int warp = tid >> 5;
    const int wm   = warp >> 2;
    const int wn   = warp & 3;
    const int bm   = blockIdx.y * 128;
    const int bn   = blockIdx.x * 128;

    const int arow = tid >> 2;
    const int acol = (tid & 3) * 4;
    const int brow = tid >> 5;
    const int bcol = (tid & 31) * 4;

    const float* gA0 = A + (size_t)(bm + arow)      * K + acol;
    const float* gA1 = A + (size_t)(bm + arow + 64) * K + acol;
    const float* gB0 = Bm + (size_t)brow       * N + bn + bcol;
    const float* gB1 = Bm + (size_t)(brow + 8) * N + bn + bcol;

    float acc[4][4][4];
#pragma unroll
    for (int i = 0; i < 4; i++)
#pragma unroll
        for (int j = 0; j < 4; j++)
#pragma unroll
            for (int c = 0; c < 4; c++) acc[i][j][c] = 0.f;

    const int T = K >> 4;
    {
        float4 a0 = *(const float4*)gA0;
        float4 a1 = *(const float4*)gA1;
        float4 b0 = *(const float4*)gB0;
        float4 b1 = *(const float4*)gB1;
        *(uint4*)&As[0][arow][acol]      = make_uint4(f2tf(a0.x),f2tf(a0.y),f2tf(a0.z),f2tf(a0.w));
        *(uint4*)&As[0][arow+64][acol]   = make_uint4(f2tf(a1.x),f2tf(a1.y),f2tf(a1.z),f2tf(a1.w));
        *(uint4*)&Bs[0][brow][bcol]      = make_uint4(f2tf(b0.x),f2tf(b0.y),f2tf(b0.z),f2tf(b0.w));
        *(uint4*)&Bs[0][brow+8][bcol]    = make_uint4(f2tf(b1.x),f2tf(b1.y),f2tf(b1.z),f2tf(b1.w));
    }
    __syncthreads();

    int buf = 0;
    for (int t = 0; t < T; t++) {
        float4 na0, na1, nb0, nb1;
        if (t + 1 < T) {
            int k0 = (t + 1) << 4;
            na0 = *(const float4*)(gA0 + k0);
            na1 = *(const float4*)(gA1 + k0);
            nb0 = *(const float4*)(gB0 + (size_t)k0 * N);
            nb1 = *(const float4*)(gB1 + (size_t)k0 * N);
        }
#pragma unroll
        for (int ks = 0; ks < 2; ks++) {
            const int kk = ks * 8;
            uint32_t af[4][4], bf[4][2];
#pragma unroll
            for (int mt = 0; mt < 4; mt++) {
                int r0 = wm*64 + mt*16 + (lane >> 2);
                int kc = kk + (lane & 3);
                af[mt][0] = As[buf][r0    ][kc];
                af[mt][1] = As[buf][r0 + 8][kc];
                af[mt][2] = As[buf][r0    ][kc + 4];
                af[mt][3] = As[buf][r0 + 8][kc + 4];
            }
#pragma unroll
            for (int nt = 0; nt < 4; nt++) {
                int cn = wn*32 + nt*8 + (lane >> 2);
                int kc = kk + (lane & 3);
                bf[nt][0] = Bs[buf][kc    ][cn];
                bf[nt][1] = Bs[buf][kc + 4][cn];
            }
#pragma unroll
            for (int mt = 0; mt < 4; mt++)
#pragma unroll
                for (int nt = 0; nt < 4; nt++)
                    mma8(acc[mt][nt], af[mt], bf[nt][0], bf[nt][1]);
        }
        if (t + 1 < T) {
            int nb = buf ^ 1;
            *(uint4*)&As[nb][arow][acol]    = make_uint4(f2tf(na0.x),f2tf(na0.y),f2tf(na0.z),f2tf(na0.w));
            *(uint4*)&As[nb][arow+64][acol] = make_uint4(f2tf(na1.x),f2tf(na1.y),f2tf(na1.z),f2tf(na1.w));
            *(uint4*)&Bs[nb][brow][bcol]    = make_uint4(f2tf(nb0.x),f2tf(nb0.y),f2tf(nb0.z),f2tf(nb0.w));
            *(uint4*)&Bs[nb][brow+8][bcol]  = make_uint4(f2tf(nb1.x),f2tf(nb1.y),f2tf(nb1.z),f2tf(nb1.w));
            __syncthreads();
            buf = nb;
        }
    }

#pragma unroll
    for (int mt = 0; mt < 4; mt++) {
#pragma unroll
        for (int nt = 0; nt < 4; nt++) {
            int m0 = bm + wm*64 + mt*16 + (lane >> 2);
            int n0 = bn + wn*32 + nt*8 + (lane & 3)*2;
#pragma unroll
            for (int half = 0; half < 2; half++) {
                int m = m0 + half*8;
                float v0 = acc[mt][nt][half*2]     + bias[n0];
                float v1 = acc[mt][nt][half*2 + 1] + bias[n0 + 1];
                if (GELU) {
                    v0 = 0.5f*v0*(1.0f + erff(v0*0.70710678118654752f));
                    v1 = 0.5f*v1*(1.0f + erff(v1*0.70710678118654752f));
                }
                if (RES) {
                    v0 += res[(size_t)m*N + n0];
                    v1 += res[(size_t)m*N + n0 + 1];
                }
                *(float2*)&C[(size_t)m*N + n0] = make_float2(v0, v1);
            }
        }
    }
}

// ---------------- tensor-core flash attention ----------------
// grid (SS/64, NH, BB), 128 threads (4 warps). Warp w owns 16 query rows.
// smem: Ks[64][68] tf32, Vs[64][72] tf32, Ps[4][16][68] tf32, padv[64].
#define KS_PITCH 68
#define VS_PITCH 72
#define PS_PITCH 68
#define ATTN_SMEM ((64*KS_PITCH + 64*VS_PITCH + 4*16*PS_PITCH)*4 + 64*4)

__global__ __launch_bounds__(128) void attn_mma_kernel(
    const float* __restrict__ Qb, const float* __restrict__ Kb,
    const float* __restrict__ Vb, const int* __restrict__ ids,
    float* __restrict__ O, int causal)
{
    extern __shared__ __align__(16) uint32_t sm[];
    uint32_t* Ks = sm;                       // 64*68
    uint32_t* Vs = Ks + 64*KS_PITCH;         // 64*72
    uint32_t* Ps = Vs + 64*VS_PITCH;         // 4*16*68
    float* padv  = (float*)(Ps + 4*16*PS_PITCH);

    const int tid  = threadIdx.x;
    const int lane = tid & 31;
    const int warp = tid >> 5;
    const int b  = blockIdx.z, h = blockIdx.y, qt = blockIdx.x;
    const int qbase = qt * 64;
    const int r0 = lane >> 2;   // 0..7
    const int c0 = lane & 3;    // 0..3

    // Q fragments (loaded once from global, converted to tf32)
    uint32_t qf[8][4];
    {
        const float* Qg = Qb + ((size_t)(b*SS + qbase + warp*16))*D + h*DH;
#pragma unroll
        for (int ks = 0; ks < 8; ks++) {
            int d0 = ks*8 + c0;
            qf[ks][0] = f2tf(Qg[(size_t)r0*D + d0]);
            qf[ks][1] = f2tf(Qg[(size_t)(r0+8)*D + d0]);
            qf[ks][2] = f2tf(Qg[(size_t)r0*D + d0 + 4]);
            qf[ks][3] = f2tf(Qg[(size_t)(r0+8)*D + d0 + 4]);
        }
    }

    float m0 = -3.0e38f, m1 = -3.0e38f, l0 = 0.f, l1 = 0.f;
    float oacc[8][4];
#pragma unroll
    for (int nt = 0; nt < 8; nt++)
#pragma unroll
        for (int c = 0; c < 4; c++) oacc[nt][c] = 0.f;

    const int qlo = qbase + warp*16 + r0;
    uint32_t* Psw = Ps + warp*16*PS_PITCH;
    const int ktend = causal ? qt : (SS/64 - 1);

    for (int kt = 0; kt <= ktend; kt++) {
        const int kbase = kt*64;
        const float* Kg = Kb + ((size_t)(b*SS + kbase))*D + h*DH;
        const float* Vg = Vb + ((size_t)(b*SS + kbase))*D + h*DH;
#pragma unroll
        for (int i = 0; i < 8; i++) {
            int linear = tid + 128*i;
            int row = linear >> 4;
            int col = (linear & 15) * 4;
            float4 kv = *(const float4*)(Kg + (size_t)row*D + col);
            float4 vv = *(const float4*)(Vg + (size_t)row*D + col);
            *(uint4*)&Ks[row*KS_PITCH + col] = make_uint4(f2tf(kv.x),f2tf(kv.y),f2tf(kv.z),f2tf(kv.w));
            *(uint4*)&Vs[row*VS_PITCH + col] = make_uint4(f2tf(vv.x),f2tf(vv.y),f2tf(vv.z),f2tf(vv.w));
        }
        if (tid < 64)
            padv[tid] = (ids[b*SS + kbase + tid] == 0) ? NEGV : 0.f;
        __syncthreads();

        // ---- S = Q K^T ----
        float sacc[8][4];
#pragma unroll
        for (int nt = 0; nt < 8; nt++)
#pragma unroll
            for (int c = 0; c < 4; c++) sacc[nt][c] = 0.f;
#pragma unroll
        for (int ks = 0; ks < 8; ks++) {
            const int kc = ks*8 + c0;
#pragma unroll
            for (int nt = 0; nt < 8; nt++) {
                uint32_t b0 = Ks[(nt*8 + r0)*KS_PITCH + kc];
                uint32_t b1 = Ks[(nt*8 + r0)*KS_PITCH + kc + 4];
                mma8(sacc[nt], qf[ks], b0, b1);
            }
        }

        // ---- mask + online softmax ----
        float tmax0 = -3.0e38f, tmax1 = -3.0e38f;
#pragma unroll
        for (int nt = 0; nt < 8; nt++) {
            int cA = nt*8 + c0*2;
            float pv0 = padv[cA], pv1 = padv[cA+1];
            sacc[nt][0] = sacc[nt][0]*0.125f + pv0;
            sacc[nt][1] = sacc[nt][1]*0.125f + pv1;
            sacc[nt][2] = sacc[nt][2]*0.125f + pv0;
            sacc[nt][3] = sacc[nt][3]*0.125f + pv1;
            if (causal && kt == qt) {
                int g0 = kbase + cA, g1 = g0 + 1;
                if (g0 > qlo)     sacc[nt][0] += NEGV;
                if (g1 > qlo)     sacc[nt][1] += NEGV;
                if (g0 > qlo + 8) sacc[nt][2] += NEGV;
                if (g1 > qlo + 8) sacc[nt][3] += NEGV;
            }
            tmax0 = fmaxf(tmax0, fmaxf(sacc[nt][0], sacc[nt][1]));
            tmax1 = fmaxf(tmax1, fmaxf(sacc[nt][2], sacc[nt][3]));
        }
        tmax0 = fmaxf(tmax0, __shfl_xor_sync(0xffffffffu, tmax0, 1));
        tmax0 = fmaxf(tmax0, __shfl_xor_sync(0xffffffffu, tmax0, 2));
        tmax1 = fmaxf(tmax1, __shfl_xor_sync(0xffffffffu, tmax1, 1));
        tmax1 = fmaxf(tmax1, __shfl_xor_sync(0xffffffffu, tmax1, 2));

        float mn0 = fmaxf(m0, tmax0), mn1 = fmaxf(m1, tmax1);
        float corr0 = __expf(m0 - mn0), corr1 = __expf(m1 - mn1);
        m0 = mn0; m1 = mn1;

        float ts0 = 0.f, ts1 = 0.f;
#pragma unroll
        for (int nt = 0; nt < 8; nt++) {
            float p0 = __expf(sacc[nt][0] - m0);
            float p1 = __expf(sacc[nt][1] - m0);
            float p2 = __expf(sacc[nt][2] - m1);
            float p3 = __expf(sacc[nt][3] - m1);
            ts0 += p0 + p1; ts1 += p2 + p3;
            *(uint2*)&Psw[r0*PS_PITCH + nt*8 + c0*2]     = make_uint2(f2tf(p0), f2tf(p1));
            *(uint2*)&Psw[(r0+8)*PS_PITCH + nt*8 + c0*2] = make_uint2(f2tf(p2), f2tf(p3));
        }
        ts0 += __shfl_xor_sync(0xffffffffu, ts0, 1);
        ts0 += __shfl_xor_sync(0xffffffffu, ts0, 2);
        ts1 += __shfl_xor_sync(0xffffffffu, ts1, 1);
        ts1 += __shfl_xor_sync(0xffffffffu, ts1, 2);
        l0 = l0*corr0 + ts0;
        l1 = l1*corr1 + ts1;

#pragma unroll
        for (int nt = 0; nt < 8; nt++) {
            oacc[nt][0] *= corr0; oacc[nt][1] *= corr0;
            oacc[nt][2] *= corr1; oacc[nt][3] *= corr1;
        }
        __syncwarp();

        // ---- O += P V ----
#pragma unroll
        for (int ks = 0; ks < 8; ks++) {
            const int kc = ks*8 + c0;
            uint32_t af[4];
            af[0] = Psw[r0*PS_PITCH + kc];
            af[1] = Psw[(r0+8)*PS_PITCH + kc];
            af[2] = Psw[r0*PS_PITCH + kc + 4];
            af[3] = Psw[(r0+8)*PS_PITCH + kc + 4];
#pragma unroll
            for (int nt = 0; nt < 8; nt++) {
                uint32_t b0 = Vs[kc*VS_PITCH + nt*8 + r0];
                uint32_t b1 = Vs[(kc + 4)*VS_PITCH + nt*8 + r0];
                mma8(oacc[nt], af, b0, b1);
            }
        }
        __syncthreads();
    }

    // ---- epilogue ----
    float inv0 = 1.f / l0, inv1 = 1.f / l1;
    float* Og = O + ((size_t)(b*SS + qbase + warp*16))*D + h*DH;
#pragma unroll
    for (int nt = 0; nt < 8; nt++) {
        int dcol = nt*8 + c0*2;
        *(float2*)&Og[(size_t)r0*D + dcol] =
            make_float2(oacc[nt][0]*inv0, oacc[nt][1]*inv0);
        *(float2*)&Og[(size_t)(r0+8)*D + dcol] =
            make_float2(oacc[nt][2]*inv1, oacc[nt][3]*inv1);
    }
}

// ---------------- host ----------------
extern "C" void kernel_launch(void* const* d_in, const int* in_sizes, int n_in,
                              void* d_out, int out_size)
{
    const float* emb  = (const float*)d_in[0];
    const int*   iids = (const int*)  d_in[1];
    const int*   tids = (const int*)  d_in[2];
    const float* tok  = (const float*)d_in[3];
    const float* pos  = (const float*)d_in[4];
    const float* ln1g = (const float*)d_in[5];
    const float* ln1b = (const float*)d_in[6];
    const float* q1w  = (const float*)d_in[7];
    const float* q1b  = (const float*)d_in[8];
    const float* k1w  = (const float*)d_in[9];
    const float* k1b  = (const float*)d_in[10];
    const float* v1w  = (const float*)d_in[11];
    const float* v1b  = (const float*)d_in[12];
    const float* o1w  = (const float*)d_in[13];
    const float* o1b  = (const float*)d_in[14];
    const float* ln2g = (const float*)d_in[15];
    const float* ln2b = (const float*)d_in[16];
    const float* q2w  = (const float*)d_in[17];
    const float* q2b  = (const float*)d_in[18];
    const float* k2w  = (const float*)d_in[19];
    const float* k2b  = (const float*)d_in[20];
    const float* v2w  = (const float*)d_in[21];
    const float* v2b  = (const float*)d_in[22];
    const float* o2w  = (const float*)d_in[23];
    const float* o2b  = (const float*)d_in[24];
    const float* ln3g = (const float*)d_in[25];
    const float* ln3b = (const float*)d_in[26];
    const float* w1   = (const float*)d_in[27];
    const float* b1   = (const float*)d_in[28];
    const float* w2   = (const float*)d_in[29];
    const float* b2   = (const float*)d_in[30];
    float* out = (float*)d_out;

    float *xln, *q, *k, *v, *ao, *h, *hln, *r, *z, *mid;
    cudaGetSymbolAddress((void**)&xln, g_xln);
    cudaGetSymbolAddress((void**)&q,   g_q);
    cudaGetSymbolAddress((void**)&k,   g_k);
    cudaGetSymbolAddress((void**)&v,   g_v);
    cudaGetSymbolAddress((void**)&ao,  g_ao);
    cudaGetSymbolAddress((void**)&h,   g_h);
    cudaGetSymbolAddress((void**)&hln, g_hln);
    cudaGetSymbolAddress((void**)&r,   g_r);
    cudaGetSymbolAddress((void**)&z,   g_z);
    cudaGetSymbolAddress((void**)&mid, g_mid);

    cudaFuncSetAttribute(attn_mma_kernel,
                         cudaFuncAttributeMaxDynamicSharedMemorySize, ATTN_SMEM);

    dim3 gProj(D/128, MTOK/128);        // (8, 32)
    dim3 gMlp1(4*D/128, MTOK/128);      // (32, 32)
    dim3 gAttn(SS/64, NH, BB);          // (32, 16, 2)

    // embedding + LN1
    embed_ln_kernel<<<MTOK, 256>>>(tids, tok, pos, ln1g, ln1b, xln);
    // self-attention q/k/v projections
    mma_gemm<0,0><<<gProj, 256>>>(xln, q1w, q1b, nullptr, q, MTOK, D, D);
    mma_gemm<0,0><<<gProj, 256>>>(xln, k1w, k1b, nullptr, k, MTOK, D, D);
    mma_gemm<0,0><<<gProj, 256>>>(xln, v1w, v1b, nullptr, v, MTOK, D, D);
    // causal self-attention (pad mask over target_ids)
    attn_mma_kernel<<<gAttn, 128, ATTN_SMEM>>>(q, k, v, tids, ao, 1);
    // out-proj + residual
    mma_gemm<0,1><<<gProj, 256>>>(ao, o1w, o1b, xln, h, MTOK, D, D);
    // LN2
    ln_kernel<<<MTOK, 256>>>(h, ln2g, ln2b, hln);
    // cross-attention projections
    mma_gemm<0,0><<<gProj, 256>>>(hln, q2w, q2b, nullptr, q, MTOK, D, D);
    mma_gemm<0,0><<<gProj, 256>>>(emb, k2w, k2b, nullptr, k, MTOK, D, D);
    mma_gemm<0,0><<<gProj, 256>>>(emb, v2w, v2b, nullptr, v, MTOK, D, D);
    // cross-attention (pad mask over input_ids)
    attn_mma_kernel<<<gAttn, 128, ATTN_SMEM>>>(q, k, v, iids, ao, 0);
    // out-proj + residual
    mma_gemm<0,1><<<gProj, 256>>>(ao, o2w, o2b, hln, r, MTOK, D, D);
    // LN3
    ln_kernel<<<MTOK, 256>>>(r, ln3g, ln3b, z);
    // MLP
    mma_gemm<1,0><<<gMlp1, 256>>>(z, w1, b1, nullptr, mid, MTOK, 4*D, D);
    mma_gemm<0,1><<<gProj, 256>>>(mid, w2, b2, r, out, MTOK, D, 4*D);
}

// round 8
// speedup vs baseline: 4.1842x; 1.1513x over previous
#include <cuda_runtime.h>
#include <math.h>
#include <stdint.h>

#define D 1024
#define NH 16
#define DH 64
#define BB 2
#define SS 2048
#define MTOK (BB*SS)       // 4096
#define NEGV -1000000000.0f

// ---------------- scratch (device globals; no allocations) ----------------
__device__ float g_xln[MTOK*D];
__device__ float g_q[MTOK*D];
__device__ float g_k[MTOK*D];
__device__ float g_v[MTOK*D];
__device__ float g_ao[MTOK*D];
__device__ float g_h[MTOK*D];
__device__ float g_hln[MTOK*D];
__device__ float g_r[MTOK*D];
__device__ float g_z[MTOK*D];
__device__ float g_mid[(size_t)MTOK*4*D];

__device__ __forceinline__ uint32_t f2tf(float x){
    uint32_t r; asm("cvt.rna.tf32.f32 %0, %1;" : "=r"(r) : "f"(x)); return r;
}
__device__ __forceinline__ void mma8(float* c, const uint32_t* a, uint32_t b0, uint32_t b1){
    asm volatile(
        "mma.sync.aligned.m16n8k8.row.col.f32.tf32.tf32.f32 "
        "{%0,%1,%2,%3}, {%4,%5,%6,%7}, {%8,%9}, {%0,%1,%2,%3};"
        : "+f"(c[0]), "+f"(c[1]), "+f"(c[2]), "+f"(c[3])
        : "r"(a[0]), "r"(a[1]), "r"(a[2]), "r"(a[3]), "r"(b0), "r"(b1));
}
__device__ __forceinline__ void cpa16(uint32_t s, const void* g){
    asm volatile("cp.async.cg.shared.global [%0], [%1], 16;" :: "r"(s), "l"(g));
}

// ---------------- fused embedding + LayerNorm1 ----------------
__global__ __launch_bounds__(256) void embed_ln_kernel(
    const int* __restrict__ tids, const float* __restrict__ tok,
    const float* __restrict__ pos, const float* __restrict__ gam,
    const float* __restrict__ bet, float* __restrict__ out)
{
    int row = blockIdx.x;
    int s   = row % SS;
    int t   = tids[row];
    const float* te = tok + (size_t)t * D;
    const float* pe = pos + (size_t)s * D;
    float v[4];
    float sum = 0.f, sq = 0.f;
#pragma unroll
    for (int i = 0; i < 4; i++) {
        int d = threadIdx.x + 256*i;
        float x = te[d] + pe[d];
        v[i] = x; sum += x; sq += x*x;
    }
    __shared__ float s1[256], s2[256];
    int tid = threadIdx.x;
    s1[tid] = sum; s2[tid] = sq; __syncthreads();
    for (int o = 128; o > 0; o >>= 1) {
        if (tid < o) { s1[tid] += s1[tid+o]; s2[tid] += s2[tid+o]; }
        __syncthreads();
    }
    float mu  = s1[0] * (1.f/D);
    float var = s2[0] * (1.f/D) - mu*mu;
    float rs  = rsqrtf(var + 1e-5f);
#pragma unroll
    for (int i = 0; i < 4; i++) {
        int d = threadIdx.x + 256*i;
        out[(size_t)row*D + d] = (v[i]-mu)*rs*gam[d] + bet[d];
    }
}

// ---------------- generic LayerNorm ----------------
__global__ __launch_bounds__(256) void ln_kernel(
    const float* __restrict__ X, const float* __restrict__ gam,
    const float* __restrict__ bet, float* __restrict__ out)
{
    int row = blockIdx.x;
    const float* x = X + (size_t)row*D;
    float v[4];
    float sum = 0.f, sq = 0.f;
#pragma unroll
    for (int i = 0; i < 4; i++) {
        int d = threadIdx.x + 256*i;
        float xx = x[d];
        v[i] = xx; sum += xx; sq += xx*xx;
    }
    __shared__ float s1[256], s2[256];
    int tid = threadIdx.x;
    s1[tid] = sum; s2[tid] = sq; __syncthreads();
    for (int o = 128; o > 0; o >>= 1) {
        if (tid < o) { s1[tid] += s1[tid+o]; s2[tid] += s2[tid+o]; }
        __syncthreads();
    }
    float mu  = s1[0] * (1.f/D);
    float var = s2[0] * (1.f/D) - mu*mu;
    float rs  = rsqrtf(var + 1e-5f);
#pragma unroll
    for (int i = 0; i < 4; i++) {
        int d = threadIdx.x + 256*i;
        out[(size_t)row*D + d] = (v[i]-mu)*rs*gam[d] + bet[d];
    }
}

// ---------------- tf32 tensor-core GEMM, 3-stage cp.async pipeline ----------
// C[M,N] = A[M,K] @ B[K,N] + bias [, GELU] [, + res]
// 128x128 CTA tile, BK=16, 256 threads (8 warps 2x4), warp tile 64x32.
// As pitch 20 (conflict-free A frags), Bs pitch 136 (conflict-free B frags).
#define A_PITCH 20
#define B_PITCH 136
#define A_STAGE (128*A_PITCH)            // 2560 u32
#define B_STAGE (16*B_PITCH)             // 2176 u32
#define GEMM_SMEM ((3*A_STAGE + 3*B_STAGE)*4)   // 56832 B

template<int GELU, int RES>
__global__ __launch_bounds__(256) void mma_gemm(
    const float* __restrict__ A, const float* __restrict__ Bm,
    const float* __restrict__ bias, const float* __restrict__ res,
    float* __restrict__ C, int M, int N, int K)
{
    extern __shared__ __align__(16) uint32_t dyn[];
    uint32_t* smA = dyn;
    uint32_t* smB = dyn + 3*A_STAGE;

    const int tid  = threadIdx.x;
    const int lane = tid & 31;
    const int warp = tid >> 5;
    const int wm   = warp >> 2;
    const int wn   = warp & 3;
    const int bm   = blockIdx.y * 128;
    const int bn   = blockIdx.x * 128;
    const int r0   = lane >> 2;
    const int c0   = lane & 3;

    // async-copy mapping
    const int ar = tid >> 2,  ac = (tid & 3) * 4;    // A: rows ar, ar+64
    const int br = tid >> 5,  bc = (tid & 31) * 4;   // B: rows br, br+8

    uint32_t saA, saB;
    {
        saA = (uint32_t)__cvta_generic_to_shared(smA);
        saB = (uint32_t)__cvta_generic_to_shared(smB);
    }

#define ISSUE_TILE(stage, t) do{                                              \
    int k0_ = (t) << 4;                                                       \
    uint32_t sA_ = saA + (uint32_t)(stage)*A_STAGE*4;                         \
    cpa16(sA_ + (ar*A_PITCH + ac)*4,      A + (size_t)(bm+ar)*K + k0_ + ac);  \
    cpa16(sA_ + ((ar+64)*A_PITCH + ac)*4, A + (size_t)(bm+ar+64)*K + k0_ + ac);\
    uint32_t sB_ = saB + (uint32_t)(stage)*B_STAGE*4;                         \
    cpa16(sB_ + (br*B_PITCH + bc)*4,      Bm + (size_t)(k0_+br)*N + bn + bc); \
    cpa16(sB_ + ((br+8)*B_PITCH + bc)*4,  Bm + (size_t)(k0_+br+8)*N + bn + bc);\
    asm volatile("cp.async.commit_group;");                                   \
}while(0)

    float acc[4][4][4];
#pragma unroll
    for (int i = 0; i < 4; i++)
#pragma unroll
        for (int j = 0; j < 4; j++)
#pragma unroll
            for (int c = 0; c < 4; c++) acc[i][j][c] = 0.f;

    const int T = K >> 4;
    ISSUE_TILE(0, 0);
    ISSUE_TILE(1, 1);

    int buf = 0;
    for (int t = 0; t < T; t++) {
        asm volatile("cp.async.wait_group 1;");
        __syncthreads();
        if (t + 2 < T) ISSUE_TILE((t+2)%3, t+2);

        const uint32_t* Ab = smA + buf*A_STAGE;
        const uint32_t* Bb = smB + buf*B_STAGE;
#pragma unroll
        for (int ks = 0; ks < 2; ks++) {
            const int kk = ks * 8;
            uint32_t af[4][4], bf[4][2];
#pragma unroll
            for (int mt = 0; mt < 4; mt++) {
                int rr = wm*64 + mt*16 + r0;
                int kc = kk + c0;
                af[mt][0] = Ab[rr*A_PITCH + kc];
                af[mt][1] = Ab[(rr+8)*A_PITCH + kc];
                af[mt][2] = Ab[rr*A_PITCH + kc + 4];
                af[mt][3] = Ab[(rr+8)*A_PITCH + kc + 4];
            }
#pragma unroll
            for (int nt = 0; nt < 4; nt++) {
                int cn = wn*32 + nt*8 + r0;
                int kc = kk + c0;
                bf[nt][0] = Bb[kc*B_PITCH + cn];
                bf[nt][1] = Bb[(kc+4)*B_PITCH + cn];
            }
#pragma unroll
            for (int mt = 0; mt < 4; mt++)
#pragma unroll
                for (int nt = 0; nt < 4; nt++)
                    mma8(acc[mt][nt], af[mt], bf[nt][0], bf[nt][1]);
        }
        buf = (buf + 1) % 3;
        __syncthreads();
    }
#undef ISSUE_TILE

    // epilogue
#pragma unroll
    for (int mt = 0; mt < 4; mt++) {
#pragma unroll
        for (int nt = 0; nt < 4; nt++) {
            int m0 = bm + wm*64 + mt*16 + r0;
            int n0 = bn + wn*32 + nt*8 + c0*2;
#pragma unroll
            for (int half = 0; half < 2; half++) {
                int m = m0 + half*8;
                float v0 = acc[mt][nt][half*2]     + bias[n0];
                float v1 = acc[mt][nt][half*2 + 1] + bias[n0 + 1];
                if (GELU) {
                    v0 = 0.5f*v0*(1.0f + erff(v0*0.70710678118654752f));
                    v1 = 0.5f*v1*(1.0f + erff(v1*0.70710678118654752f));
                }
                if (RES) {
                    v0 += res[(size_t)m*N + n0];
                    v1 += res[(size_t)m*N + n0 + 1];
                }
                *(float2*)&C[(size_t)m*N + n0] = make_float2(v0, v1);
            }
        }
    }
}

// ---------------- tensor-core flash attention (unchanged from R4) ----------
#define KS_PITCH 68
#define VS_PITCH 72
#define PS_PITCH 68
#define ATTN_SMEM ((64*KS_PITCH + 64*VS_PITCH + 4*16*PS_PITCH)*4 + 64*4)

__global__ __launch_bounds__(128) void attn_mma_kernel(
    const float* __restrict__ Qb, const float* __restrict__ Kb,
    const float* __restrict__ Vb, const int* __restrict__ ids,
    float* __restrict__ O, int causal)
{
    extern __shared__ __align__(16) uint32_t sm[];
    uint32_t* Ks = sm;
    uint32_t* Vs = Ks + 64*KS_PITCH;
    uint32_t* Ps = Vs + 64*VS_PITCH;
    float* padv  = (float*)(Ps + 4*16*PS_PITCH);

    const int tid  = threadIdx.x;
    const int lane = tid & 31;
    const int warp = tid >> 5;
    const int b  = blockIdx.z, h = blockIdx.y, qt = blockIdx.x;
    const int qbase = qt * 64;
    const int r0 = lane >> 2;
    const int c0 = lane & 3;

    uint32_t qf[8][4];
    {
        const float* Qg = Qb + ((size_t)(b*SS + qbase + warp*16))*D + h*DH;
#pragma unroll
        for (int ks = 0; ks < 8; ks++) {
            int d0 = ks*8 + c0;
            qf[ks][0] = f2tf(Qg[(size_t)r0*D + d0]);
            qf[ks][1] = f2tf(Qg[(size_t)(r0+8)*D + d0]);
            qf[ks][2] = f2tf(Qg[(size_t)r0*D + d0 + 4]);
            qf[ks][3] = f2tf(Qg[(size_t)(r0+8)*D + d0 + 4]);
        }
    }

    float m0 = -3.0e38f, m1 = -3.0e38f, l0 = 0.f, l1 = 0.f;
    float oacc[8][4];
#pragma unroll
    for (int nt = 0; nt < 8; nt++)
#pragma unroll
        for (int c = 0; c < 4; c++) oacc[nt][c] = 0.f;

    const int qlo = qbase + warp*16 + r0;
    uint32_t* Psw = Ps + warp*16*PS_PITCH;
    const int ktend = causal ? qt : (SS/64 - 1);

    for (int kt = 0; kt <= ktend; kt++) {
        const int kbase = kt*64;
        const float* Kg = Kb + ((size_t)(b*SS + kbase))*D + h*DH;
        const float* Vg = Vb + ((size_t)(b*SS + kbase))*D + h*DH;
#pragma unroll
        for (int i = 0; i < 8; i++) {
            int linear = tid + 128*i;
            int row = linear >> 4;
            int col = (linear & 15) * 4;
            float4 kv = *(const float4*)(Kg + (size_t)row*D + col);
            float4 vv = *(const float4*)(Vg + (size_t)row*D + col);
            *(uint4*)&Ks[row*KS_PITCH + col] = make_uint4(f2tf(kv.x),f2tf(kv.y),f2tf(kv.z),f2tf(kv.w));
            *(uint4*)&Vs[row*VS_PITCH + col] = make_uint4(f2tf(vv.x),f2tf(vv.y),f2tf(vv.z),f2tf(vv.w));
        }
        if (tid < 64)
            padv[tid] = (ids[b*SS + kbase + tid] == 0) ? NEGV : 0.f;
        __syncthreads();

        float sacc[8][4];
#pragma unroll
        for (int nt = 0; nt < 8; nt++)
#pragma unroll
            for (int c = 0; c < 4; c++) sacc[nt][c] = 0.f;
#pragma unroll
        for (int ks = 0; ks < 8; ks++) {
            const int kc = ks*8 + c0;
#pragma unroll
            for (int nt = 0; nt < 8; nt++) {
                uint32_t b0 = Ks[(nt*8 + r0)*KS_PITCH + kc];
                uint32_t b1 = Ks[(nt*8 + r0)*KS_PITCH + kc + 4];
                mma8(sacc[nt], qf[ks], b0, b1);
            }
        }

        float tmax0 = -3.0e38f, tmax1 = -3.0e38f;
#pragma unroll
        for (int nt = 0; nt < 8; nt++) {
            int cA = nt*8 + c0*2;
            float pv0 = padv[cA], pv1 = padv[cA+1];
            sacc[nt][0] = sacc[nt][0]*0.125f + pv0;
            sacc[nt][1] = sacc[nt][1]*0.125f + pv1;
            sacc[nt][2] = sacc[nt][2]*0.125f + pv0;
            sacc[nt][3] = sacc[nt][3]*0.125f + pv1;
            if (causal && kt == qt) {
                int g0 = kbase + cA, g1 = g0 + 1;
                if (g0 > qlo)     sacc[nt][0] += NEGV;
                if (g1 > qlo)     sacc[nt][1] += NEGV;
                if (g0 > qlo + 8) sacc[nt][2] += NEGV;
                if (g1 > qlo + 8) sacc[nt][3] += NEGV;
            }
            tmax0 = fmaxf(tmax0, fmaxf(sacc[nt][0], sacc[nt][1]));
            tmax1 = fmaxf(tmax1, fmaxf(sacc[nt][2], sacc[nt][3]));
        }
        tmax0 = fmaxf(tmax0, __shfl_xor_sync(0xffffffffu, tmax0, 1));
        tmax0 = fmaxf(tmax0, __shfl_xor_sync(0xffffffffu, tmax0, 2));
        tmax1 = fmaxf(tmax1, __shfl_xor_sync(0xffffffffu, tmax1, 1));
        tmax1 = fmaxf(tmax1, __shfl_xor_sync(0xffffffffu, tmax1, 2));

        float mn0 = fmaxf(m0, tmax0), mn1 = fmaxf(m1, tmax1);
        float corr0 = __expf(m0 - mn0), corr1 = __expf(m1 - mn1);
        m0 = mn0; m1 = mn1;

        float ts0 = 0.f, ts1 = 0.f;
#pragma unroll
        for (int nt = 0; nt < 8; nt++) {
            float p0 = __expf(sacc[nt][0] - m0);
            float p1 = __expf(sacc[nt][1] - m0);
            float p2 = __expf(sacc[nt][2] - m1);
            float p3 = __expf(sacc[nt][3] - m1);
            ts0 += p0 + p1; ts1 += p2 + p3;
            *(uint2*)&Psw[r0*PS_PITCH + nt*8 + c0*2]     = make_uint2(f2tf(p0), f2tf(p1));
            *(uint2*)&Psw[(r0+8)*PS_PITCH + nt*8 + c0*2] = make_uint2(f2tf(p2), f2tf(p3));
        }
        ts0 += __shfl_xor_sync(0xffffffffu, ts0, 1);
        ts0 += __shfl_xor_sync(0xffffffffu, ts0, 2);
        ts1 += __shfl_xor_sync(0xffffffffu, ts1, 1);
        ts1 += __shfl_xor_sync(0xffffffffu, ts1, 2);
        l0 = l0*corr0 + ts0;
        l1 = l1*corr1 + ts1;

#pragma unroll
        for (int nt = 0; nt < 8; nt++) {
            oacc[nt][0] *= corr0; oacc[nt][1] *= corr0;
            oacc[nt][2] *= corr1; oacc[nt][3] *= corr1;
        }
        __syncwarp();

#pragma unroll
        for (int ks = 0; ks < 8; ks++) {
            const int kc = ks*8 + c0;
            uint32_t af[4];
            af[0] = Psw[r0*PS_PITCH + kc];
            af[1] = Psw[(r0+8)*PS_PITCH + kc];
            af[2] = Psw[r0*PS_PITCH + kc + 4];
            af[3] = Psw[(r0+8)*PS_PITCH + kc + 4];
#pragma unroll
            for (int nt = 0; nt < 8; nt++) {
                uint32_t b0 = Vs[kc*VS_PITCH + nt*8 + r0];
                uint32_t b1 = Vs[(kc + 4)*VS_PITCH + nt*8 + r0];
                mma8(oacc[nt], af, b0, b1);
            }
        }
        __syncthreads();
    }

    float inv0 = 1.f / l0, inv1 = 1.f / l1;
    float* Og = O + ((size_t)(b*SS + qbase + warp*16))*D + h*DH;
#pragma unroll
    for (int nt = 0; nt < 8; nt++) {
        int dcol = nt*8 + c0*2;
        *(float2*)&Og[(size_t)r0*D + dcol] =
            make_float2(oacc[nt][0]*inv0, oacc[nt][1]*inv0);
        *(float2*)&Og[(size_t)(r0+8)*D + dcol] =
            make_float2(oacc[nt][2]*inv1, oacc[nt][3]*inv1);
    }
}

// ---------------- host ----------------
extern "C" void kernel_launch(void* const* d_in, const int* in_sizes, int n_in,
                              void* d_out, int out_size)
{
    const float* emb  = (const float*)d_in[0];
    const int*   iids = (const int*)  d_in[1];
    const int*   tids = (const int*)  d_in[2];
    const float* tok  = (const float*)d_in[3];
    const float* pos  = (const float*)d_in[4];
    const float* ln1g = (const float*)d_in[5];
    const float* ln1b = (const float*)d_in[6];
    const float* q1w  = (const float*)d_in[7];
    const float* q1b  = (const float*)d_in[8];
    const float* k1w  = (const float*)d_in[9];
    const float* k1b  = (const float*)d_in[10];
    const float* v1w  = (const float*)d_in[11];
    const float* v1b  = (const float*)d_in[12];
    const float* o1w  = (const float*)d_in[13];
    const float* o1b  = (const float*)d_in[14];
    const float* ln2g = (const float*)d_in[15];
    const float* ln2b = (const float*)d_in[16];
    const float* q2w  = (const float*)d_in[17];
    const float* q2b  = (const float*)d_in[18];
    const float* k2w  = (const float*)d_in[19];
    const float* k2b  = (const float*)d_in[20];
    const float* v2w  = (const float*)d_in[21];
    const float* v2b  = (const float*)d_in[22];
    const float* o2w  = (const float*)d_in[23];
    const float* o2b  = (const float*)d_in[24];
    const float* ln3g = (const float*)d_in[25];
    const float* ln3b = (const float*)d_in[26];
    const float* w1   = (const float*)d_in[27];
    const float* b1   = (const float*)d_in[28];
    const float* w2   = (const float*)d_in[29];
    const float* b2   = (const float*)d_in[30];
    float* out = (float*)d_out;

    float *xln, *q, *k, *v, *ao, *h, *hln, *r, *z, *mid;
    cudaGetSymbolAddress((void**)&xln, g_xln);
    cudaGetSymbolAddress((void**)&q,   g_q);
    cudaGetSymbolAddress((void**)&k,   g_k);
    cudaGetSymbolAddress((void**)&v,   g_v);
    cudaGetSymbolAddress((void**)&ao,  g_ao);
    cudaGetSymbolAddress((void**)&h,   g_h);
    cudaGetSymbolAddress((void**)&hln, g_hln);
    cudaGetSymbolAddress((void**)&r,   g_r);
    cudaGetSymbolAddress((void**)&z,   g_z);
    cudaGetSymbolAddress((void**)&mid, g_mid);

    cudaFuncSetAttribute(attn_mma_kernel,
                         cudaFuncAttributeMaxDynamicSharedMemorySize, ATTN_SMEM);
    cudaFuncSetAttribute(mma_gemm<0,0>,
                         cudaFuncAttributeMaxDynamicSharedMemorySize, GEMM_SMEM);
    cudaFuncSetAttribute(mma_gemm<0,1>,
                         cudaFuncAttributeMaxDynamicSharedMemorySize, GEMM_SMEM);
    cudaFuncSetAttribute(mma_gemm<1,0>,
                         cudaFuncAttributeMaxDynamicSharedMemorySize, GEMM_SMEM);

    dim3 gProj(D/128, MTOK/128);        // (8, 32)
    dim3 gMlp1(4*D/128, MTOK/128);      // (32, 32)
    dim3 gAttn(SS/64, NH, BB);          // (32, 16, 2)

    // embedding + LN1
    embed_ln_kernel<<<MTOK, 256>>>(tids, tok, pos, ln1g, ln1b, xln);
    // self-attention q/k/v projections
    mma_gemm<0,0><<<gProj, 256, GEMM_SMEM>>>(xln, q1w, q1b, nullptr, q, MTOK, D, D);
    mma_gemm<0,0><<<gProj, 256, GEMM_SMEM>>>(xln, k1w, k1b, nullptr, k, MTOK, D, D);
    mma_gemm<0,0><<<gProj, 256, GEMM_SMEM>>>(xln, v1w, v1b, nullptr, v, MTOK, D, D);
    // causal self-attention (pad mask over target_ids)
    attn_mma_kernel<<<gAttn, 128, ATTN_SMEM>>>(q, k, v, tids, ao, 1);
    // out-proj + residual
    mma_gemm<0,1><<<gProj, 256, GEMM_SMEM>>>(ao, o1w, o1b, xln, h, MTOK, D, D);
    // LN2
    ln_kernel<<<MTOK, 256>>>(h, ln2g, ln2b, hln);
    // cross-attention projections
    mma_gemm<0,0><<<gProj, 256, GEMM_SMEM>>>(hln, q2w, q2b, nullptr, q, MTOK, D, D);
    mma_gemm<0,0><<<gProj, 256, GEMM_SMEM>>>(emb, k2w, k2b, nullptr, k, MTOK, D, D);
    mma_gemm<0,0><<<gProj, 256, GEMM_SMEM>>>(emb, v2w, v2b, nullptr, v, MTOK, D, D);
    // cross-attention (pad mask over input_ids)
    attn_mma_kernel<<<gAttn, 128, ATTN_SMEM>>>(q, k, v, iids, ao, 0);
    // out-proj + residual
    mma_gemm<0,1><<<gProj, 256, GEMM_SMEM>>>(ao, o2w, o2b, hln, r, MTOK, D, D);
    // LN3
    ln_kernel<<<MTOK, 256>>>(r, ln3g, ln3b, z);
    // MLP
    mma_gemm<1,0><<<gMlp1, 256, GEMM_SMEM>>>(z, w1, b1, nullptr, mid, MTOK, 4*D, D);
    mma_gemm<0,1><<<gProj, 256, GEMM_SMEM>>>(mid, w2, b2, r, out, MTOK, D, 4*D);
}